// round 15
// baseline (speedup 1.0000x reference)
#include <cuda_runtime.h>
#include <math.h>

// Problem constants (fixed by the reference setup)
#define BB   256
#define NA   24      // atoms
#define NN   23      // neighbors per atom (N-1)
#define NP   253     // pairs = NN*(NN-1)/2
#define KR   16
#define KA   32
#define NF   (KR + KA)
#define RCR  5.2f
#define RCA  3.5f
#define PI_F 3.14159265358979323846f
#define LOG2E 1.4426950408889634f

#define SCALE_UP 100.0f
#define SCALE_DN 7.888609052210118e-31f   // 2^-100

typedef unsigned long long u64;

static __device__ __forceinline__ float ex2_approx(float x) {
    float r; asm("ex2.approx.ftz.f32 %0, %1;" : "=f"(r) : "f"(x)); return r;
}
static __device__ __forceinline__ float lg2_approx(float x) {
    float r; asm("lg2.approx.ftz.f32 %0, %1;" : "=f"(r) : "f"(x)); return r;
}
static __device__ __forceinline__ float sqrt_approx(float x) {
    float r; asm("sqrt.approx.ftz.f32 %0, %1;" : "=f"(r) : "f"(x)); return r;
}
static __device__ __forceinline__ float rcp_approx(float x) {
    float r; asm("rcp.approx.ftz.f32 %0, %1;" : "=f"(r) : "f"(x)); return r;
}
// ---- packed f32x2 helpers (sm_103a; ptxas never emits these from C++) ----
static __device__ __forceinline__ u64 pack2(float lo, float hi) {
    u64 r; asm("mov.b64 %0, {%1, %2};" : "=l"(r) : "f"(lo), "f"(hi)); return r;
}
static __device__ __forceinline__ void unpack2(u64 v, float& lo, float& hi) {
    asm("mov.b64 {%0, %1}, %2;" : "=f"(lo), "=f"(hi) : "l"(v));
}
static __device__ __forceinline__ u64 mul2(u64 a, u64 b) {
    u64 d; asm("mul.rn.f32x2 %0, %1, %2;" : "=l"(d) : "l"(a), "l"(b)); return d;
}
static __device__ __forceinline__ u64 fma2v(u64 a, u64 b, u64 c) {
    u64 d; asm("fma.rn.f32x2 %0, %1, %2, %3;" : "=l"(d) : "l"(a), "l"(b), "l"(c)); return d;
}

// Compile-time pair table: pair p -> (r | c<<8), rows of triu_indices(NN, k=1)
struct PT { unsigned short v[256]; };
static constexpr PT make_pt() {
    PT t{};
    int p = 0;
    for (int r = 0; r < NN; ++r)
        for (int c = r + 1; c < NN; ++c) { t.v[p] = (unsigned short)(r | (c << 8)); ++p; }
    for (; p < 256; ++p) t.v[p] = (unsigned short)(0 | (1 << 8));  // padding pairs
    return t;
}
static __device__ const PT d_pt = make_pt();

// Per-site shared slab. Row stride 36 floats: STS consecutive (conflict free),
// acc LDS.128 rows land on disjoint bank groups.
struct __align__(16) WarpBuf {
    float4 nb1[24];                       // {rx, ry, rz, invd}
    float2 nb2[24];                       // {d, fA}
    float2 nb3[24];                       // {d, fR}
    __align__(16) float powb[2][4 * 36];  // (1+cos(theta-a))^32, double buffered
    __align__(16) float radf[2][8 * 36];  // envelope ladder
};
#define SMEM_BYTES (16 * (int)sizeof(WarpBuf))

struct G4 { float cs, sn, dz, fw; };

static __device__ __forceinline__ G4 pair_geom(const WarpBuf& W, int p) {
    const unsigned short rc = d_pt.v[p];
    const int r = rc & 0xFF, c = rc >> 8;
    float4 A1 = W.nb1[r];
    float4 B1 = W.nb1[c];
    float2 A2 = W.nb2[r];
    float2 B2 = W.nb2[c];
    float dot = A1.x * B1.x + A1.y * B1.y + A1.z * B1.z;
    float cs = dot * A1.w * B1.w;
    cs = fminf(fmaxf(cs, -1.0f + 1e-7f), 1.0f - 1e-7f);
    G4 g;
    g.cs = cs;
    g.sn = sqrt_approx(fmaxf(0.0f, 1.0f - cs * cs));
    g.dz = 0.5f * (A2.x + B2.x);
    g.fw = (p < NP) ? A2.y * B2.y : 0.0f;
    return g;
}

static __device__ __forceinline__ void emit_pair(
    WarpBuf& W, int par, int l, const G4& g,
    u64 cp01, u64 cp23, u64 sp01, u64 sp23,
    u64 S01, u64 S23, u64 S45,
    float sz0, float eAc, float c1c, float rr0)
{
    // 4 angular powers (1+cos(theta-a))^32 via packed repeated squaring
    const u64 ONE2 = 0x3f8000003f800000ULL;
    u64 cs2 = pack2(g.cs, g.cs), sn2 = pack2(g.sn, g.sn);
    u64 x01 = fma2v(cs2, cp01, fma2v(sn2, sp01, ONE2));
    u64 x23 = fma2v(cs2, cp23, fma2v(sn2, sp23, ONE2));
    x01 = mul2(x01, x01); x01 = mul2(x01, x01); x01 = mul2(x01, x01);
    x01 = mul2(x01, x01); x01 = mul2(x01, x01);
    x23 = mul2(x23, x23); x23 = mul2(x23, x23); x23 = mul2(x23, x23);
    x23 = mul2(x23, x23); x23 = mul2(x23, x23);
    float p0, p1, p2, p3;
    unpack2(x01, p0, p1); unpack2(x23, p2, p3);
    float* pw = W.powb[par];
    pw[0 * 36 + l] = p0;  pw[1 * 36 + l] = p1;
    pw[2 * 36 + l] = p2;  pw[3 * 36 + l] = p3;

    // 8 radial envelopes: 2^100-scaled geometric ladder (2 MUFU)
    float u = g.dz - sz0;
    float A = ex2_approx(fmaf(-eAc * u, u, SCALE_UP));
    float R = ex2_approx(c1c * u);
    float unsc = g.fw * SCALE_DN;
    float v0 = A * unsc;
    float v1 = v0 * R * rr0;
    u64 R22 = pack2(R * R, R * R);
    u64 v01 = pack2(v0, v1);
    u64 v23 = mul2(v01, mul2(R22, S01));
    u64 v45 = mul2(v23, mul2(R22, S23));
    u64 v67 = mul2(v45, mul2(R22, S45));
    float f2, f3, f4, f5, f6, f7;
    unpack2(v23, f2, f3); unpack2(v45, f4, f5); unpack2(v67, f6, f7);
    float* rf = W.radf[par];
    rf[0 * 36 + l] = v0;  rf[1 * 36 + l] = v1;
    rf[2 * 36 + l] = f2;  rf[3 * 36 + l] = f3;
    rf[4 * 36 + l] = f4;  rf[5 * 36 + l] = f5;
    rf[6 * 36 + l] = f6;  rf[7 * 36 + l] = f7;
}

static __device__ __forceinline__ void acc_chunk(
    const WarpBuf& W, int par, int rowP, int rowR, u64& accA, u64& accB)
{
    const ulonglong2* pp = reinterpret_cast<const ulonglong2*>(W.powb[par] + rowP);
    const ulonglong2* rp = reinterpret_cast<const ulonglong2*>(W.radf[par] + rowR);
    #pragma unroll
    for (int t = 0; t < 8; ++t) {
        ulonglong2 P = pp[t];
        ulonglong2 Q = rp[t];
        accA = fma2v(P.x, Q.x, accA);
        accB = fma2v(P.y, Q.y, accB);
    }
}

// Cold generic path (accurate libm) — isolated from the hot path.
static __device__ __noinline__ void generic_g3(
    const WarpBuf& W, const float* Zt, const float* SZt,
    const float* EAt, const float* SAt,
    float g2acc, float* osite, int l)
{
    const float zk  = Zt[l];
    const float sZk = SZt[l];
    const float e2k = -EAt[l] * LOG2E;
    float sak, cak;
    sincosf(SAt[l], &sak, &cak);
    float acc = 0.0f;
    for (int p = 0; p < NP; ++p) {
        const unsigned short rc = d_pt.v[p];
        const int r = rc & 0xFF, c = rc >> 8;
        float4 A1 = W.nb1[r];
        float4 B1 = W.nb1[c];
        float2 A2 = W.nb2[r];
        float2 B2 = W.nb2[c];
        float dot = A1.x * B1.x + A1.y * B1.y + A1.z * B1.z;
        float cs = dot * A1.w * B1.w;
        cs = fminf(fmaxf(cs, -1.0f + 1e-7f), 1.0f - 1e-7f);
        float sn = sqrtf(fmaxf(0.0f, 1.0f - cs * cs));
        float dz = 0.5f * (A2.x + B2.x);
        float fw = A2.y * B2.y;
        float cosang = fmaf(cs, cak, sn * sak);
        float lg = lg2_approx(1.0f + cosang);
        float dd = dz - sZk;
        float e  = fmaf(zk, lg, (e2k * dd) * dd);
        acc = fmaf(ex2_approx(e), fw, acc);
    }
    osite[KR + l] = exp2f(1.0f - zk) * acc;
    if (l < KR) osite[l] = g2acc;
}

static __device__ __forceinline__ void neighbor_setup(
    WarpBuf& W, const float* coords, int b, int i, int l)
{
    if (l < NN) {
        const int j = (l < i) ? l : l + 1;
        const float* ci = coords + (size_t)(b * NA + i) * 3;
        const float* cj = coords + (size_t)(b * NA + j) * 3;
        float rx = ci[0] - cj[0];
        float ry = ci[1] - cj[1];
        float rz = ci[2] - cj[2];
        float d  = sqrt_approx(rx * rx + ry * ry + rz * rz);
        float fR = 0.5f * (__cosf(d * (PI_F / RCR)) + 1.0f);
        float fA = 0.5f * (__cosf(d * (PI_F / RCA)) + 1.0f);
        W.nb1[l] = make_float4(rx, ry, rz, rcp_approx(d));
        W.nb2[l] = make_float2(d, fA);
        W.nb3[l] = make_float2(d, fR);
    }
}

static __device__ __forceinline__ float g2_compute(
    const WarpBuf& W, const float* EtaRt, const float* ShfRt, int l)
{
    const int k = l & 15;
    const float erk = -EtaRt[k] * LOG2E;
    const float sr  = ShfRt[k];
    float acc = 0.0f;
    for (int j = (l >> 4); j < NN; j += 2) {
        float2 df = W.nb3[j];
        float t = df.x - sr;
        acc += ex2_approx((erk * t) * t) * df.y;
    }
    return acc + __shfl_xor_sync(0xffffffffu, acc, 16);
}

__global__ __launch_bounds__(256)
void ani_feature_kernel(const float* __restrict__ coords,     // (B, NA, 3)
                        const int*   __restrict__ atom_types, // (NA,)
                        const float* __restrict__ EtaR,       // (T, KR)
                        const float* __restrict__ ShfR,
                        const float* __restrict__ Zeta,       // (T, KA)
                        const float* __restrict__ ShfZ,
                        const float* __restrict__ EtaA,
                        const float* __restrict__ ShfA,
                        float*       __restrict__ out)        // (B, NA, 48)
{
    const int warp = threadIdx.x >> 5;
    const int l    = threadIdx.x & 31;
    // One warp = two sites with the SAME atom index i (same type -> shared
    // constants), adjacent batches: site0 = (2*bp)*NA + i, site1 = site0 + NA.
    const int k  = blockIdx.x * 8 + warp;      // pair index, 0..3071
    const int i  = k % NA;
    const int bp = k / NA;
    const int b0 = 2 * bp;
    const int site0 = b0 * NA + i;
    const int site1 = site0 + NA;

    extern __shared__ char smem_raw[];
    WarpBuf* wb = reinterpret_cast<WarpBuf*>(smem_raw);
    WarpBuf& W0 = wb[warp * 2];
    WarpBuf& W1 = wb[warp * 2 + 1];

    const int ti = atom_types[i];              // uniform broadcast LDG

    const float* Zt  = Zeta + (size_t)ti * KA;
    const float* SZt = ShfZ + (size_t)ti * KA;
    const float* EAt = EtaA + (size_t)ti * KA;
    const float* SAt = ShfA + (size_t)ti * KA;

    // ---- structure check (warp-uniform ballot) ----
    float sz0 = SZt[0];
    float dlt = (SZt[7] - sz0) * (1.0f / 7.0f);
    float eA0 = EAt[0];
    bool ok = (Zt[l] == 32.0f)
           && (EAt[l] == eA0)
           && (SAt[l] == SAt[l & ~7])
           && (SZt[l] == SZt[l & 7])
           && (fabsf(SZt[l & 7] - (sz0 + (float)(l & 7) * dlt)) < 1e-4f);
    const bool fast = (__ballot_sync(0xffffffffu, ok) == 0xffffffffu);

    // ---- Phase 1: neighbor geometry for both sites ----
    neighbor_setup(W0, coords, b0,     i, l);
    neighbor_setup(W1, coords, b0 + 1, i, l);
    __syncwarp();

    // ---- Phase 2: radial G2 for both sites ----
    const float* EtaRt = EtaR + (size_t)ti * KR;
    const float* ShfRt = ShfR + (size_t)ti * KR;
    float g2a = g2_compute(W0, EtaRt, ShfRt, l);
    float g2b = g2_compute(W1, EtaRt, ShfRt, l);

    float* osite0 = out + (size_t)site0 * NF;
    float* osite1 = out + (size_t)site1 * NF;

    if (!fast) {                               // cold, isolated path
        generic_g3(W0, Zt, SZt, EAt, SAt, g2a, osite0, l);
        generic_g3(W1, Zt, SZt, EAt, SAt, g2b, osite1, l);
        return;
    }

    // ---- derived constants, pre-packed into registers (shared by sites) ----
    const float eAc = eA0 * LOG2E;
    const float c1c = 2.0f * eAc * dlt;
    u64 cp01, cp23, sp01, sp23, S01, S23, S45;
    float rr0;
    {
        float a  = SAt[(l & 3) * 8];                   // lanes 0..3: the 4 angles
        float cb = __cosf(a);
        float sb = __sinf(a);
        cp01 = pack2(__shfl_sync(0xffffffffu, cb, 0), __shfl_sync(0xffffffffu, cb, 1));
        cp23 = pack2(__shfl_sync(0xffffffffu, cb, 2), __shfl_sync(0xffffffffu, cb, 3));
        sp01 = pack2(__shfl_sync(0xffffffffu, sb, 0), __shfl_sync(0xffffffffu, sb, 1));
        sp23 = pack2(__shfl_sync(0xffffffffu, sb, 2), __shfl_sync(0xffffffffu, sb, 3));
        float ed2 = eAc * dlt * dlt;
        float rr  = ex2_approx(-ed2 * (float)(2 * (l & 7) + 1));   // lanes 0..6 valid
        float Sv  = rr * __shfl_down_sync(0xffffffffu, rr, 1);
        rr0 = __shfl_sync(0xffffffffu, rr, 0);
        S01 = pack2(__shfl_sync(0xffffffffu, Sv, 0), __shfl_sync(0xffffffffu, Sv, 1));
        S23 = pack2(__shfl_sync(0xffffffffu, Sv, 2), __shfl_sync(0xffffffffu, Sv, 3));
        S45 = pack2(__shfl_sync(0xffffffffu, Sv, 4), __shfl_sync(0xffffffffu, Sv, 5));
    }

    // ---- Software-pipelined dual-site chunk loop: 1 syncwarp per chunk ----
    u64 aA0 = 0ULL, aB0 = 0ULL;    // site0 packed accumulators
    u64 aA1 = 0ULL, aB1 = 0ULL;    // site1 packed accumulators

    {
        G4 ga = pair_geom(W0, l);
        G4 gb = pair_geom(W1, l);
        emit_pair(W0, 0, l, ga, cp01, cp23, sp01, sp23, S01, S23, S45, sz0, eAc, c1c, rr0);
        emit_pair(W1, 0, l, gb, cp01, cp23, sp01, sp23, S01, S23, S45, sz0, eAc, c1c, rr0);
    }
    __syncwarp();

    int par = 0;
    const int rowP = (l >> 3) * 36;            // pow row offset for this lane
    const int rowR = (l & 7) * 36;             // radf row offset for this lane
    for (int ch = 0; ch < 7; ++ch) {
        // prefetch next chunk geometry for both sites (overlaps row reads)
        G4 ga = pair_geom(W0, (ch + 1) * 32 + l);
        G4 gb = pair_geom(W1, (ch + 1) * 32 + l);

        // accumulate current chunk, both sites (independent chains)
        acc_chunk(W0, par, rowP, rowR, aA0, aB0);
        acc_chunk(W1, par, rowP, rowR, aA1, aB1);

        // emit next chunk into the other buffers
        emit_pair(W0, par ^ 1, l, ga, cp01, cp23, sp01, sp23, S01, S23, S45, sz0, eAc, c1c, rr0);
        emit_pair(W1, par ^ 1, l, gb, cp01, cp23, sp01, sp23, S01, S23, S45, sz0, eAc, c1c, rr0);
        __syncwarp();
        par ^= 1;
    }
    acc_chunk(W0, par, rowP, rowR, aA0, aB0);
    acc_chunk(W1, par, rowP, rowR, aA1, aB1);

    // ---- output (fully warp-local) ----
    {
        u64 t0 = fma2v(aA0, 0x3f8000003f800000ULL, aB0);
        float x0, x1;
        unpack2(t0, x0, x1);
        osite0[KR + l] = 0x1p-31f * (x0 + x1);   // 2^(1-zeta), zeta=32
        if (l < KR) osite0[l] = g2a;
    }
    {
        u64 t1 = fma2v(aA1, 0x3f8000003f800000ULL, aB1);
        float y0, y1;
        unpack2(t1, y0, y1);
        osite1[KR + l] = 0x1p-31f * (y0 + y1);
        if (l < KR) osite1[l] = g2b;
    }
}

extern "C" void kernel_launch(void* const* d_in, const int* in_sizes, int n_in,
                              void* d_out, int out_size) {
    const float* coords     = (const float*)d_in[0];
    const int*   atom_types = (const int*)  d_in[1];
    const float* EtaR       = (const float*)d_in[2];
    const float* ShfR       = (const float*)d_in[3];
    const float* Zeta       = (const float*)d_in[4];
    const float* ShfZ       = (const float*)d_in[5];
    const float* EtaA       = (const float*)d_in[6];
    const float* ShfA       = (const float*)d_in[7];
    float* out = (float*)d_out;

    cudaFuncSetAttribute(ani_feature_kernel,
                         cudaFuncAttributeMaxDynamicSharedMemorySize, SMEM_BYTES);
    // 3072 site-pairs, 8 warps/block -> 384 blocks, single wave at 3 blocks/SM
    ani_feature_kernel<<<384, 256, SMEM_BYTES>>>(coords, atom_types, EtaR, ShfR,
                                                 Zeta, ShfZ, EtaA, ShfA, out);
}

// round 16
// speedup vs baseline: 1.9904x; 1.9904x over previous
#include <cuda_runtime.h>
#include <math.h>

// Problem constants (fixed by the reference setup)
#define BB   256
#define NA   24      // atoms
#define NN   23      // neighbors per atom (N-1)
#define NP   253     // pairs = NN*(NN-1)/2
#define KR   16
#define KA   32
#define NF   (KR + KA)
#define RCR  5.2f
#define RCA  3.5f
#define PI_F 3.14159265358979323846f
#define LOG2E 1.4426950408889634f

#define SCALE_UP 100.0f
#define SCALE_DN 7.888609052210118e-31f   // 2^-100

typedef unsigned long long u64;

static __device__ __forceinline__ float ex2_approx(float x) {
    float r; asm("ex2.approx.ftz.f32 %0, %1;" : "=f"(r) : "f"(x)); return r;
}
static __device__ __forceinline__ float lg2_approx(float x) {
    float r; asm("lg2.approx.ftz.f32 %0, %1;" : "=f"(r) : "f"(x)); return r;
}
static __device__ __forceinline__ float sqrt_approx(float x) {
    float r; asm("sqrt.approx.ftz.f32 %0, %1;" : "=f"(r) : "f"(x)); return r;
}
static __device__ __forceinline__ float rcp_approx(float x) {
    float r; asm("rcp.approx.ftz.f32 %0, %1;" : "=f"(r) : "f"(x)); return r;
}
// ---- packed f32x2 helpers (sm_103a; ptxas never emits these from C++) ----
static __device__ __forceinline__ u64 pack2(float lo, float hi) {
    u64 r; asm("mov.b64 %0, {%1, %2};" : "=l"(r) : "f"(lo), "f"(hi)); return r;
}
static __device__ __forceinline__ void unpack2(u64 v, float& lo, float& hi) {
    asm("mov.b64 {%0, %1}, %2;" : "=f"(lo), "=f"(hi) : "l"(v));
}
static __device__ __forceinline__ u64 mul2(u64 a, u64 b) {
    u64 d; asm("mul.rn.f32x2 %0, %1, %2;" : "=l"(d) : "l"(a), "l"(b)); return d;
}
static __device__ __forceinline__ u64 fma2v(u64 a, u64 b, u64 c) {
    u64 d; asm("fma.rn.f32x2 %0, %1, %2, %3;" : "=l"(d) : "l"(a), "l"(b), "l"(c)); return d;
}

// Compile-time pair table: pair p -> (r | c<<8), rows of triu_indices(NN, k=1)
struct PT { unsigned short v[256]; };
static constexpr PT make_pt() {
    PT t{};
    int p = 0;
    for (int r = 0; r < NN; ++r)
        for (int c = r + 1; c < NN; ++c) { t.v[p] = (unsigned short)(r | (c << 8)); ++p; }
    for (; p < 256; ++p) t.v[p] = (unsigned short)(0 | (1 << 8));  // padding pairs
    return t;
}
static __device__ const PT d_pt = make_pt();

// Per-warp shared slab: neighbor tables + reduction scratch.
// accS row stride 34 floats (136 B, 8-aligned for STS.64); column reads are
// at worst 2-way bank conflicted.
struct __align__(16) Slab {
    float4 nb1[24];          // {rx, ry, rz, invd}
    float2 nb2[24];          // {d, fA}
    float2 nb3[24];          // {d, fR}
    float  accS[32 * 34];    // per-lane 4x8 feature matrices (f = a*8+z)
};

// Cold generic path (accurate libm) — isolated from the hot path.
static __device__ __noinline__ void generic_g3(
    const Slab& W, const float* Zt, const float* SZt,
    const float* EAt, const float* SAt,
    float g2acc, float* osite, int l)
{
    const float zk  = Zt[l];
    const float sZk = SZt[l];
    const float e2k = -EAt[l] * LOG2E;
    float sak, cak;
    sincosf(SAt[l], &sak, &cak);
    float acc = 0.0f;
    for (int p = 0; p < NP; ++p) {
        const unsigned short rc = d_pt.v[p];
        const int r = rc & 0xFF, c = rc >> 8;
        float4 A1 = W.nb1[r];
        float4 B1 = W.nb1[c];
        float2 A2 = W.nb2[r];
        float2 B2 = W.nb2[c];
        float dot = A1.x * B1.x + A1.y * B1.y + A1.z * B1.z;
        float cs = dot * A1.w * B1.w;
        cs = fminf(fmaxf(cs, -1.0f + 1e-7f), 1.0f - 1e-7f);
        float sn = sqrtf(fmaxf(0.0f, 1.0f - cs * cs));
        float dz = 0.5f * (A2.x + B2.x);
        float fw = A2.y * B2.y;
        float cosang = fmaf(cs, cak, sn * sak);
        float lg = lg2_approx(1.0f + cosang);
        float dd = dz - sZk;
        float e  = fmaf(zk, lg, (e2k * dd) * dd);
        acc = fmaf(ex2_approx(e), fw, acc);
    }
    osite[KR + l] = exp2f(1.0f - zk) * acc;
    if (l < KR) osite[l] = g2acc;
}

__global__ __launch_bounds__(256)
void ani_feature_kernel(const float* __restrict__ coords,     // (B, NA, 3)
                        const int*   __restrict__ atom_types, // (NA,)
                        const float* __restrict__ EtaR,       // (T, KR)
                        const float* __restrict__ ShfR,
                        const float* __restrict__ Zeta,       // (T, KA)
                        const float* __restrict__ ShfZ,
                        const float* __restrict__ EtaA,
                        const float* __restrict__ ShfA,
                        float*       __restrict__ out)        // (B, NA, 48)
{
    const int warp = threadIdx.x >> 5;
    const int l    = threadIdx.x & 31;
    const int site = blockIdx.x * 8 + warp;    // one warp = one site
    const int b = site / NA;
    const int i = site - b * NA;

    __shared__ Slab wb[8];
    Slab& W = wb[warp];

    const int ti = atom_types[i];              // uniform broadcast LDG

    const float* Zt  = Zeta + (size_t)ti * KA;
    const float* SZt = ShfZ + (size_t)ti * KA;
    const float* EAt = EtaA + (size_t)ti * KA;
    const float* SAt = ShfA + (size_t)ti * KA;

    // ---- structure check (warp-uniform ballot) ----
    float sz0 = SZt[0];
    float dlt = (SZt[7] - sz0) * (1.0f / 7.0f);
    float eA0 = EAt[0];
    bool ok = (Zt[l] == 32.0f)
           && (EAt[l] == eA0)
           && (SAt[l] == SAt[l & ~7])
           && (SZt[l] == SZt[l & 7])
           && (fabsf(SZt[l & 7] - (sz0 + (float)(l & 7) * dlt)) < 1e-4f);
    const bool fast = (__ballot_sync(0xffffffffu, ok) == 0xffffffffu);

    // ---- Phase 1: neighbor geometry (lanes 0..22; approx cos/sqrt/rcp) ----
    if (l < NN) {
        const int j = (l < i) ? l : l + 1;
        const float* ci = coords + (size_t)(b * NA + i) * 3;
        const float* cj = coords + (size_t)(b * NA + j) * 3;
        float rx = ci[0] - cj[0];
        float ry = ci[1] - cj[1];
        float rz = ci[2] - cj[2];
        float d  = sqrt_approx(rx * rx + ry * ry + rz * rz);
        float fR = 0.5f * (__cosf(d * (PI_F / RCR)) + 1.0f);
        float fA = 0.5f * (__cosf(d * (PI_F / RCA)) + 1.0f);
        W.nb1[l] = make_float4(rx, ry, rz, rcp_approx(d));
        W.nb2[l] = make_float2(d, fA);
        W.nb3[l] = make_float2(d, fR);
    }
    __syncwarp();

    // ---- Phase 2: radial G2 (lane = feature l%16, half = l/16; shfl combine) ----
    float g2acc = 0.0f;
    {
        const int k = l & 15;
        const float erk = -EtaR[ti * KR + k] * LOG2E;
        const float sr  = ShfR[ti * KR + k];
        for (int j = (l >> 4); j < NN; j += 2) {
            float2 df = W.nb3[j];
            float t = df.x - sr;
            g2acc += ex2_approx((erk * t) * t) * df.y;
        }
        g2acc += __shfl_xor_sync(0xffffffffu, g2acc, 16);
    }

    float* osite = out + (size_t)site * NF;

    if (!fast) {                               // cold, isolated path
        generic_g3(W, Zt, SZt, EAt, SAt, g2acc, osite, l);
        return;
    }

    // ---- derived constants in registers (warp-uniform scalars) ----
    const float eAc = eA0 * LOG2E;
    const float c1c = 2.0f * eAc * dlt;
    float cA0, cA1, cA2, cA3, sA0, sA1, sA2, sA3, rr0;
    u64 S01, S23, S45;
    {
        float a  = SAt[(l & 3) * 8];                   // lanes 0..3: the 4 angles
        float cb = __cosf(a);
        float sb = __sinf(a);
        cA0 = __shfl_sync(0xffffffffu, cb, 0); sA0 = __shfl_sync(0xffffffffu, sb, 0);
        cA1 = __shfl_sync(0xffffffffu, cb, 1); sA1 = __shfl_sync(0xffffffffu, sb, 1);
        cA2 = __shfl_sync(0xffffffffu, cb, 2); sA2 = __shfl_sync(0xffffffffu, sb, 2);
        cA3 = __shfl_sync(0xffffffffu, cb, 3); sA3 = __shfl_sync(0xffffffffu, sb, 3);
        float ed2 = eAc * dlt * dlt;
        float rr  = ex2_approx(-ed2 * (float)(2 * (l & 7) + 1));   // lanes 0..6 valid
        float Sv  = rr * __shfl_down_sync(0xffffffffu, rr, 1);
        rr0 = __shfl_sync(0xffffffffu, rr, 0);
        S01 = pack2(__shfl_sync(0xffffffffu, Sv, 0), __shfl_sync(0xffffffffu, Sv, 1));
        S23 = pack2(__shfl_sync(0xffffffffu, Sv, 2), __shfl_sync(0xffffffffu, Sv, 3));
        S45 = pack2(__shfl_sync(0xffffffffu, Sv, 4), __shfl_sync(0xffffffffu, Sv, 5));
    }

    // ---- Pair loop: each lane owns pair p = ch*32 + l; rank-1 updates into
    //      16 register-resident packed accumulators (4 angular x 8 radial).
    u64 a00 = 0, a01 = 0, a02 = 0, a03 = 0;
    u64 a10 = 0, a11 = 0, a12 = 0, a13 = 0;
    u64 a20 = 0, a21 = 0, a22 = 0, a23 = 0;
    u64 a30 = 0, a31 = 0, a32 = 0, a33 = 0;

    #pragma unroll 4
    for (int ch = 0; ch < 8; ++ch) {
        const int p = ch * 32 + l;
        const unsigned short rc = d_pt.v[p];
        const int r = rc & 0xFF, c = rc >> 8;
        float4 A1 = W.nb1[r];
        float4 B1 = W.nb1[c];
        float2 A2 = W.nb2[r];
        float2 B2 = W.nb2[c];
        float dot = A1.x * B1.x + A1.y * B1.y + A1.z * B1.z;
        float cs = dot * A1.w * B1.w;
        cs = fminf(fmaxf(cs, -1.0f + 1e-7f), 1.0f - 1e-7f);
        float sn = sqrt_approx(fmaxf(0.0f, 1.0f - cs * cs));
        float dz = 0.5f * (A2.x + B2.x);
        float fw = (p < NP) ? A2.y * B2.y : 0.0f;

        // 4 angular powers (1+cos(theta-a))^32, packed repeated squaring
        float x0 = 1.0f + fmaf(cs, cA0, sn * sA0);
        float x1 = 1.0f + fmaf(cs, cA1, sn * sA1);
        float x2 = 1.0f + fmaf(cs, cA2, sn * sA2);
        float x3 = 1.0f + fmaf(cs, cA3, sn * sA3);
        u64 x01 = pack2(x0, x1), x23 = pack2(x2, x3);
        x01 = mul2(x01, x01); x01 = mul2(x01, x01); x01 = mul2(x01, x01);
        x01 = mul2(x01, x01); x01 = mul2(x01, x01);
        x23 = mul2(x23, x23); x23 = mul2(x23, x23); x23 = mul2(x23, x23);
        x23 = mul2(x23, x23); x23 = mul2(x23, x23);
        float p0, p1, p2, p3;
        unpack2(x01, p0, p1); unpack2(x23, p2, p3);
        u64 P0 = pack2(p0, p0), P1 = pack2(p1, p1);
        u64 P2 = pack2(p2, p2), P3 = pack2(p3, p3);

        // 8 radial envelopes, 2^100-scaled geometric ladder (2 MUFU)
        float u = dz - sz0;
        float A = ex2_approx(fmaf(-eAc * u, u, SCALE_UP));
        float R = ex2_approx(c1c * u);
        float unsc = fw * SCALE_DN;
        float v0 = A * unsc;
        float v1 = v0 * R * rr0;
        float R2 = R * R;
        u64 R22 = pack2(R2, R2);
        u64 v01 = pack2(v0, v1);
        u64 v23 = mul2(v01, mul2(R22, S01));
        u64 v45 = mul2(v23, mul2(R22, S23));
        u64 v67 = mul2(v45, mul2(R22, S45));

        // rank-1 update: acc[a][zz] += P_a * v_zz
        a00 = fma2v(P0, v01, a00); a01 = fma2v(P0, v23, a01);
        a02 = fma2v(P0, v45, a02); a03 = fma2v(P0, v67, a03);
        a10 = fma2v(P1, v01, a10); a11 = fma2v(P1, v23, a11);
        a12 = fma2v(P1, v45, a12); a13 = fma2v(P1, v67, a13);
        a20 = fma2v(P2, v01, a20); a21 = fma2v(P2, v23, a21);
        a22 = fma2v(P2, v45, a22); a23 = fma2v(P2, v67, a23);
        a30 = fma2v(P3, v01, a30); a31 = fma2v(P3, v23, a31);
        a32 = fma2v(P3, v45, a32); a33 = fma2v(P3, v67, a33);
    }

    // ---- transpose-reduce via smem scratch (one syncwarp) ----
    {
        u64* as64 = reinterpret_cast<u64*>(W.accS + l * 34);
        as64[0]  = a00; as64[1]  = a01; as64[2]  = a02; as64[3]  = a03;
        as64[4]  = a10; as64[5]  = a11; as64[6]  = a12; as64[7]  = a13;
        as64[8]  = a20; as64[9]  = a21; as64[10] = a22; as64[11] = a23;
        as64[12] = a30; as64[13] = a31; as64[14] = a32; as64[15] = a33;
    }
    __syncwarp();
    float s = 0.0f;
    #pragma unroll
    for (int q = 0; q < 32; ++q) s += W.accS[q * 34 + l];

    // ---- output ----
    osite[KR + l] = 0x1p-31f * s;              // 2^(1-zeta), zeta=32
    if (l < KR) osite[l] = g2acc;
}

extern "C" void kernel_launch(void* const* d_in, const int* in_sizes, int n_in,
                              void* d_out, int out_size) {
    const float* coords     = (const float*)d_in[0];
    const int*   atom_types = (const int*)  d_in[1];
    const float* EtaR       = (const float*)d_in[2];
    const float* ShfR       = (const float*)d_in[3];
    const float* Zeta       = (const float*)d_in[4];
    const float* ShfZ       = (const float*)d_in[5];
    const float* EtaA       = (const float*)d_in[6];
    const float* ShfA       = (const float*)d_in[7];
    float* out = (float*)d_out;

    ani_feature_kernel<<<(BB * NA) / 8, 256>>>(coords, atom_types, EtaR, ShfR,
                                               Zeta, ShfZ, EtaA, ShfA, out);
}

// round 17
// speedup vs baseline: 2.2263x; 1.1185x over previous
#include <cuda_runtime.h>
#include <math.h>

// Problem constants (fixed by the reference setup)
#define BB   256
#define NA   24      // atoms
#define NN   23      // neighbors per atom (N-1)
#define NP   253     // pairs = NN*(NN-1)/2
#define KR   16
#define KA   32
#define NF   (KR + KA)
#define RCR  5.2f
#define RCA  3.5f
#define PI_F 3.14159265358979323846f
#define LOG2E 1.4426950408889634f

#define SCALE_UP 100.0f
#define SCALE_DN 7.888609052210118e-31f   // 2^-100

typedef unsigned long long u64;

static __device__ __forceinline__ float ex2_approx(float x) {
    float r; asm("ex2.approx.ftz.f32 %0, %1;" : "=f"(r) : "f"(x)); return r;
}
static __device__ __forceinline__ float lg2_approx(float x) {
    float r; asm("lg2.approx.ftz.f32 %0, %1;" : "=f"(r) : "f"(x)); return r;
}
static __device__ __forceinline__ float sqrt_approx(float x) {
    float r; asm("sqrt.approx.ftz.f32 %0, %1;" : "=f"(r) : "f"(x)); return r;
}
static __device__ __forceinline__ float rcp_approx(float x) {
    float r; asm("rcp.approx.ftz.f32 %0, %1;" : "=f"(r) : "f"(x)); return r;
}
// ---- packed f32x2 helpers (sm_103a; ptxas never emits these from C++) ----
static __device__ __forceinline__ u64 pack2(float lo, float hi) {
    u64 r; asm("mov.b64 %0, {%1, %2};" : "=l"(r) : "f"(lo), "f"(hi)); return r;
}
static __device__ __forceinline__ void unpack2(u64 v, float& lo, float& hi) {
    asm("mov.b64 {%0, %1}, %2;" : "=f"(lo), "=f"(hi) : "l"(v));
}
static __device__ __forceinline__ u64 mul2(u64 a, u64 b) {
    u64 d; asm("mul.rn.f32x2 %0, %1, %2;" : "=l"(d) : "l"(a), "l"(b)); return d;
}
static __device__ __forceinline__ u64 fma2v(u64 a, u64 b, u64 c) {
    u64 d; asm("fma.rn.f32x2 %0, %1, %2, %3;" : "=l"(d) : "l"(a), "l"(b), "l"(c)); return d;
}

// Compile-time pair table: pair p -> (r | c<<8), rows of triu_indices(NN, k=1)
struct PT { unsigned short v[256]; };
static constexpr PT make_pt() {
    PT t{};
    int p = 0;
    for (int r = 0; r < NN; ++r)
        for (int c = r + 1; c < NN; ++c) { t.v[p] = (unsigned short)(r | (c << 8)); ++p; }
    for (; p < 256; ++p) t.v[p] = (unsigned short)(0 | (1 << 8));  // padding pairs
    return t;
}
static __device__ const PT d_pt = make_pt();

// Per-warp shared slab: neighbor tables + reduction scratch.
// accS row stride 34 floats (136 B, 8-aligned for STS.64); column reads are
// at worst 2-way bank conflicted.
struct __align__(16) Slab {
    float4 nb1[24];          // {rx, ry, rz, invd}
    float2 nb2[24];          // {d, fA}
    float2 nb3[24];          // {d, fR}
    float  accS[32 * 34];    // per-lane 4x8 feature matrices (f = a*8+z)
};

// Cold generic path (accurate libm) — isolated from the hot path.
static __device__ __noinline__ void generic_g3(
    const Slab& W, const float* Zt, const float* SZt,
    const float* EAt, const float* SAt,
    float g2acc, float* osite, int l)
{
    const float zk  = Zt[l];
    const float sZk = SZt[l];
    const float e2k = -EAt[l] * LOG2E;
    float sak, cak;
    sincosf(SAt[l], &sak, &cak);
    float acc = 0.0f;
    for (int p = 0; p < NP; ++p) {
        const unsigned short rc = d_pt.v[p];
        const int r = rc & 0xFF, c = rc >> 8;
        float4 A1 = W.nb1[r];
        float4 B1 = W.nb1[c];
        float2 A2 = W.nb2[r];
        float2 B2 = W.nb2[c];
        float dot = A1.x * B1.x + A1.y * B1.y + A1.z * B1.z;
        float cs = dot * A1.w * B1.w;
        cs = fminf(fmaxf(cs, -1.0f + 1e-7f), 1.0f - 1e-7f);
        float sn = sqrtf(fmaxf(0.0f, 1.0f - cs * cs));
        float dz = 0.5f * (A2.x + B2.x);
        float fw = A2.y * B2.y;
        float cosang = fmaf(cs, cak, sn * sak);
        float lg = lg2_approx(1.0f + cosang);
        float dd = dz - sZk;
        float e  = fmaf(zk, lg, (e2k * dd) * dd);
        acc = fmaf(ex2_approx(e), fw, acc);
    }
    osite[KR + l] = exp2f(1.0f - zk) * acc;
    if (l < KR) osite[l] = g2acc;
}

__global__ __launch_bounds__(256)
void ani_feature_kernel(const float* __restrict__ coords,     // (B, NA, 3)
                        const int*   __restrict__ atom_types, // (NA,)
                        const float* __restrict__ EtaR,       // (T, KR)
                        const float* __restrict__ ShfR,
                        const float* __restrict__ Zeta,       // (T, KA)
                        const float* __restrict__ ShfZ,
                        const float* __restrict__ EtaA,
                        const float* __restrict__ ShfA,
                        float*       __restrict__ out)        // (B, NA, 48)
{
    const int warp = threadIdx.x >> 5;
    const int l    = threadIdx.x & 31;
    // Persistent: warp k handles sites k and k+3072. 3072 % 24 == 0, so both
    // share atom index i -> same type -> constants computed once.
    const int k = blockIdx.x * 8 + warp;       // 0..3071
    const int i = k % NA;

    __shared__ Slab wb[8];
    Slab& W = wb[warp];

    const int ti = atom_types[i];              // uniform broadcast LDG

    const float* Zt  = Zeta + (size_t)ti * KA;
    const float* SZt = ShfZ + (size_t)ti * KA;
    const float* EAt = EtaA + (size_t)ti * KA;
    const float* SAt = ShfA + (size_t)ti * KA;

    // ---- structure check (warp-uniform ballot), once for both sites ----
    float sz0 = SZt[0];
    float dlt = (SZt[7] - sz0) * (1.0f / 7.0f);
    float eA0 = EAt[0];
    bool ok = (Zt[l] == 32.0f)
           && (EAt[l] == eA0)
           && (SAt[l] == SAt[l & ~7])
           && (SZt[l] == SZt[l & 7])
           && (fabsf(SZt[l & 7] - (sz0 + (float)(l & 7) * dlt)) < 1e-4f);
    const bool fast = (__ballot_sync(0xffffffffu, ok) == 0xffffffffu);

    // ---- derived constants (once; u64-packed angular consts) ----
    const float eAc = eA0 * LOG2E;
    const float c1c = 2.0f * eAc * dlt;
    u64 cA01 = 0, cA23 = 0, sA01 = 0, sA23 = 0, S01 = 0, S23 = 0, S45 = 0;
    float rr0 = 0.0f;
    if (fast) {
        float a  = SAt[(l & 3) * 8];                   // lanes 0..3: the 4 angles
        float cb = __cosf(a);
        float sb = __sinf(a);
        cA01 = pack2(__shfl_sync(0xffffffffu, cb, 0), __shfl_sync(0xffffffffu, cb, 1));
        cA23 = pack2(__shfl_sync(0xffffffffu, cb, 2), __shfl_sync(0xffffffffu, cb, 3));
        sA01 = pack2(__shfl_sync(0xffffffffu, sb, 0), __shfl_sync(0xffffffffu, sb, 1));
        sA23 = pack2(__shfl_sync(0xffffffffu, sb, 2), __shfl_sync(0xffffffffu, sb, 3));
        float ed2 = eAc * dlt * dlt;
        float rr  = ex2_approx(-ed2 * (float)(2 * (l & 7) + 1));   // lanes 0..6 valid
        float Sv  = rr * __shfl_down_sync(0xffffffffu, rr, 1);
        rr0 = __shfl_sync(0xffffffffu, rr, 0);
        S01 = pack2(__shfl_sync(0xffffffffu, Sv, 0), __shfl_sync(0xffffffffu, Sv, 1));
        S23 = pack2(__shfl_sync(0xffffffffu, Sv, 2), __shfl_sync(0xffffffffu, Sv, 3));
        S45 = pack2(__shfl_sync(0xffffffffu, Sv, 4), __shfl_sync(0xffffffffu, Sv, 5));
    }
    const float erk = -EtaR[ti * KR + (l & 15)] * LOG2E;   // G2 params, reused
    const float srk = ShfR[ti * KR + (l & 15)];

    #pragma unroll 1
    for (int s = 0; s < 2; ++s) {
        const int site = k + s * 3072;
        const int b = site / NA;

        // ---- Phase 1: neighbor geometry (lanes 0..22) ----
        if (l < NN) {
            const int j = (l < i) ? l : l + 1;
            const float* ci = coords + (size_t)(b * NA + i) * 3;
            const float* cj = coords + (size_t)(b * NA + j) * 3;
            float rx = ci[0] - cj[0];
            float ry = ci[1] - cj[1];
            float rz = ci[2] - cj[2];
            float d  = sqrt_approx(rx * rx + ry * ry + rz * rz);
            float fR = 0.5f * (__cosf(d * (PI_F / RCR)) + 1.0f);
            float fA = 0.5f * (__cosf(d * (PI_F / RCA)) + 1.0f);
            W.nb1[l] = make_float4(rx, ry, rz, rcp_approx(d));
            W.nb2[l] = make_float2(d, fA);
            W.nb3[l] = make_float2(d, fR);
        }
        __syncwarp();

        // ---- Phase 2: radial G2 ----
        float g2acc = 0.0f;
        for (int j = (l >> 4); j < NN; j += 2) {
            float2 df = W.nb3[j];
            float t = df.x - srk;
            g2acc += ex2_approx((erk * t) * t) * df.y;
        }
        g2acc += __shfl_xor_sync(0xffffffffu, g2acc, 16);

        float* osite = out + (size_t)site * NF;

        if (!fast) {                           // cold, isolated path
            generic_g3(W, Zt, SZt, EAt, SAt, g2acc, osite, l);
            __syncwarp();
            continue;
        }

        // ---- Pair loop: lane owns pair p = ch*32 + l; rank-1 updates into
        //      16 register-resident packed accumulators (4 angular x 8 radial).
        u64 a00 = 0, a01 = 0, a02 = 0, a03 = 0;
        u64 a10 = 0, a11 = 0, a12 = 0, a13 = 0;
        u64 a20 = 0, a21 = 0, a22 = 0, a23 = 0;
        u64 a30 = 0, a31 = 0, a32 = 0, a33 = 0;

        #pragma unroll 4
        for (int ch = 0; ch < 8; ++ch) {
            const int p = ch * 32 + l;
            const unsigned short rc = d_pt.v[p];
            const int r = rc & 0xFF, c = rc >> 8;
            float4 A1 = W.nb1[r];
            float4 B1 = W.nb1[c];
            float2 A2 = W.nb2[r];
            float2 B2 = W.nb2[c];
            float dot = A1.x * B1.x + A1.y * B1.y + A1.z * B1.z;
            float cs = dot * A1.w * B1.w;
            cs = fminf(fmaxf(cs, -1.0f + 1e-7f), 1.0f - 1e-7f);
            float sn = sqrt_approx(fmaxf(0.0f, 1.0f - cs * cs));
            float dz = 0.5f * (A2.x + B2.x);
            float fw = (p < NP) ? A2.y * B2.y : 0.0f;

            // 4 angular powers (1+cos(theta-a))^32, fully packed
            const u64 ONE2 = 0x3f8000003f800000ULL;
            u64 cs2 = pack2(cs, cs), sn2 = pack2(sn, sn);
            u64 x01 = fma2v(cs2, cA01, fma2v(sn2, sA01, ONE2));
            u64 x23 = fma2v(cs2, cA23, fma2v(sn2, sA23, ONE2));
            x01 = mul2(x01, x01); x01 = mul2(x01, x01); x01 = mul2(x01, x01);
            x01 = mul2(x01, x01); x01 = mul2(x01, x01);
            x23 = mul2(x23, x23); x23 = mul2(x23, x23); x23 = mul2(x23, x23);
            x23 = mul2(x23, x23); x23 = mul2(x23, x23);
            float p0, p1, p2, p3;
            unpack2(x01, p0, p1); unpack2(x23, p2, p3);
            u64 P0 = pack2(p0, p0), P1 = pack2(p1, p1);
            u64 P2 = pack2(p2, p2), P3 = pack2(p3, p3);

            // 8 radial envelopes, 2^100-scaled geometric ladder (2 MUFU)
            float u = dz - sz0;
            float A = ex2_approx(fmaf(-eAc * u, u, SCALE_UP));
            float R = ex2_approx(c1c * u);
            float unsc = fw * SCALE_DN;
            float v0 = A * unsc;
            float v1 = v0 * R * rr0;
            float R2 = R * R;
            u64 R22 = pack2(R2, R2);
            u64 v01 = pack2(v0, v1);
            u64 v23 = mul2(v01, mul2(R22, S01));
            u64 v45 = mul2(v23, mul2(R22, S23));
            u64 v67 = mul2(v45, mul2(R22, S45));

            // rank-1 update: acc[a][zz] += P_a * v_zz
            a00 = fma2v(P0, v01, a00); a01 = fma2v(P0, v23, a01);
            a02 = fma2v(P0, v45, a02); a03 = fma2v(P0, v67, a03);
            a10 = fma2v(P1, v01, a10); a11 = fma2v(P1, v23, a11);
            a12 = fma2v(P1, v45, a12); a13 = fma2v(P1, v67, a13);
            a20 = fma2v(P2, v01, a20); a21 = fma2v(P2, v23, a21);
            a22 = fma2v(P2, v45, a22); a23 = fma2v(P2, v67, a23);
            a30 = fma2v(P3, v01, a30); a31 = fma2v(P3, v23, a31);
            a32 = fma2v(P3, v45, a32); a33 = fma2v(P3, v67, a33);
        }

        // ---- transpose-reduce via smem scratch (one syncwarp) ----
        {
            u64* as64 = reinterpret_cast<u64*>(W.accS + l * 34);
            as64[0]  = a00; as64[1]  = a01; as64[2]  = a02; as64[3]  = a03;
            as64[4]  = a10; as64[5]  = a11; as64[6]  = a12; as64[7]  = a13;
            as64[8]  = a20; as64[9]  = a21; as64[10] = a22; as64[11] = a23;
            as64[12] = a30; as64[13] = a31; as64[14] = a32; as64[15] = a33;
        }
        __syncwarp();
        float sred = 0.0f;
        #pragma unroll
        for (int q = 0; q < 32; ++q) sred += W.accS[q * 34 + l];

        // ---- output ----
        osite[KR + l] = 0x1p-31f * sred;       // 2^(1-zeta), zeta=32
        if (l < KR) osite[l] = g2acc;
        // next site's nb writes are ordered after this site's reads: every
        // lane passed the post-store syncwarp above before reducing, and the
        // next iteration's syncwarp (after neighbor_setup) orders the rest.
    }
}

extern "C" void kernel_launch(void* const* d_in, const int* in_sizes, int n_in,
                              void* d_out, int out_size) {
    const float* coords     = (const float*)d_in[0];
    const int*   atom_types = (const int*)  d_in[1];
    const float* EtaR       = (const float*)d_in[2];
    const float* ShfR       = (const float*)d_in[3];
    const float* Zeta       = (const float*)d_in[4];
    const float* ShfZ       = (const float*)d_in[5];
    const float* EtaA       = (const float*)d_in[6];
    const float* ShfA       = (const float*)d_in[7];
    float* out = (float*)d_out;

    // 3072 persistent warps, 2 sites each -> 384 blocks, single wave
    ani_feature_kernel<<<384, 256>>>(coords, atom_types, EtaR, ShfR,
                                     Zeta, ShfZ, EtaA, ShfA, out);
}